// round 1
// baseline (speedup 1.0000x reference)
#include <cuda_runtime.h>
#include <math.h>

#define Bdim 8
#define Tdim 2048
#define Ddim 256
#define CACT 64
#define CTIME 32
#define NCOL 96
#define LABEL_ID_ 3
#define ACT_START_ 4
#define TIME_START_ 68
#define VOCAB_ 100

// device scratch (no allocations allowed)
__device__ float g_WcT[Ddim * NCOL];   // transposed combined weights [d][c]
__device__ float g_bias[NCOL];
__device__ float g_En[NCOL * Ddim];    // normalized E rows: 0..63 act, 64..95 time
__device__ float g_scal[4];            // [0] scale_act*temp_act, [1] scale_time*temp_time,
                                       // [2] alpha_act, [3] alpha_time

__device__ __forceinline__ float softplusf(float x) { return log1pf(expf(x)); }

// ---------------------------------------------------------------------------
// Prep: fold tied weights into parametric weights, normalize E rows, scalars.
// ---------------------------------------------------------------------------
__global__ void prep_kernel(const float* __restrict__ E,
                            const float* __restrict__ Wn, const float* __restrict__ bn,
                            const float* __restrict__ Wt, const float* __restrict__ bt,
                            const float* __restrict__ tsa, const float* __restrict__ tst,
                            const float* __restrict__ psa, const float* __restrict__ pst,
                            const float* __restrict__ ppa, const float* __restrict__ ppt,
                            const float* __restrict__ pta, const float* __restrict__ ptt)
{
    int tid = threadIdx.x;
    float s_ta = softplusf(*tsa);
    float s_tt = softplusf(*tst);
    if (tid == 0) {
        g_scal[0] = softplusf(*psa) * softplusf(*pta);
        g_scal[1] = softplusf(*pst) * softplusf(*ptt);
        g_scal[2] = softplusf(*ppa);
        g_scal[3] = softplusf(*ppt);
    }
    // combined weights, stored transposed [d][c]
    for (int i = tid; i < NCOL * Ddim; i += blockDim.x) {
        int c = i / Ddim, d = i % Ddim;
        float w;
        if (c < CACT) w = Wn[c * Ddim + d] + s_ta * E[(ACT_START_ + c) * Ddim + d];
        else {
            int cc = c - CACT;
            w = Wt[cc * Ddim + d] + s_tt * E[(TIME_START_ + cc) * Ddim + d];
        }
        g_WcT[d * NCOL + c] = w;
    }
    for (int c = tid; c < NCOL; c += blockDim.x)
        g_bias[c] = (c < CACT) ? bn[c] : bt[c - CACT];

    // l2-normalized class embeddings
    int wid = tid >> 5, lane = tid & 31;
    int nw = blockDim.x >> 5;
    for (int c = wid; c < NCOL; c += nw) {
        int row = (c < CACT) ? (ACT_START_ + c) : (TIME_START_ + (c - CACT));
        const float* e = E + (long)row * Ddim;
        float ss = 0.f;
        for (int d = lane; d < Ddim; d += 32) { float v = e[d]; ss += v * v; }
#pragma unroll
        for (int o = 16; o > 0; o >>= 1) ss += __shfl_xor_sync(0xffffffffu, ss, o);
        float inv = 1.0f / fmaxf(sqrtf(ss), 1e-12f);
        for (int d = lane; d < Ddim; d += 32) g_En[c * Ddim + d] = e[d] * inv;
    }
}

// ---------------------------------------------------------------------------
// Dense GEMM: out[row, 0..95] = h[row,:] @ WcT + bias.
// Block = 256 threads, 64 rows per block, thread computes 4 rows x 6 cols.
// ---------------------------------------------------------------------------
#define GROWS 64
#define HPAD 257

__global__ void gemm_kernel(const float* __restrict__ h, float* __restrict__ out)
{
    extern __shared__ float sm[];
    float* Wc = sm;                        // 256*96
    float* hs = sm + Ddim * NCOL;          // 64*257 (padded rows -> no bank conflicts)
    float* bs = hs + GROWS * HPAD;         // 96
    int tid = threadIdx.x;

    // cooperative loads
    {
        const float4* src = (const float4*)g_WcT;
        float4* dst = (float4*)Wc;
        for (int i = tid; i < (Ddim * NCOL) / 4; i += 256) dst[i] = src[i];
        for (int i = tid; i < NCOL; i += 256) bs[i] = g_bias[i];
        long base = (long)blockIdx.x * GROWS * Ddim;
        const float4* h4 = (const float4*)(h + base);
        for (int i = tid; i < (GROWS * Ddim) / 4; i += 256) {
            float4 v = h4[i];
            int el = i * 4;
            int r = el / Ddim, d = el % Ddim;
            float* p = &hs[r * HPAD + d];
            p[0] = v.x; p[1] = v.y; p[2] = v.z; p[3] = v.w;
        }
    }
    __syncthreads();

    int cx = tid & 15;   // 16 column groups x 6 cols
    int rx = tid >> 4;   // 16 row groups x 4 rows
    float acc[4][6];
#pragma unroll
    for (int j = 0; j < 4; j++)
#pragma unroll
        for (int i = 0; i < 6; i++) acc[j][i] = 0.f;

    const float* wp = Wc + cx * 6;
    const float* hp = hs + (rx * 4) * HPAD;

#pragma unroll 4
    for (int d = 0; d < Ddim; d++) {
        float2 w0 = *(const float2*)(wp + d * NCOL + 0);
        float2 w1 = *(const float2*)(wp + d * NCOL + 2);
        float2 w2 = *(const float2*)(wp + d * NCOL + 4);
        float h0 = hp[d];
        float h1 = hp[HPAD + d];
        float h2 = hp[2 * HPAD + d];
        float h3 = hp[3 * HPAD + d];
        acc[0][0] += h0 * w0.x; acc[0][1] += h0 * w0.y; acc[0][2] += h0 * w1.x;
        acc[0][3] += h0 * w1.y; acc[0][4] += h0 * w2.x; acc[0][5] += h0 * w2.y;
        acc[1][0] += h1 * w0.x; acc[1][1] += h1 * w0.y; acc[1][2] += h1 * w1.x;
        acc[1][3] += h1 * w1.y; acc[1][4] += h1 * w2.x; acc[1][5] += h1 * w2.y;
        acc[2][0] += h2 * w0.x; acc[2][1] += h2 * w0.y; acc[2][2] += h2 * w1.x;
        acc[2][3] += h2 * w1.y; acc[2][4] += h2 * w2.x; acc[2][5] += h2 * w2.y;
        acc[3][0] += h3 * w0.x; acc[3][1] += h3 * w0.y; acc[3][2] += h3 * w1.x;
        acc[3][3] += h3 * w1.y; acc[3][4] += h3 * w2.x; acc[3][5] += h3 * w2.y;
    }

    float* out_time = out + (long)Bdim * Tdim * CACT;
#pragma unroll
    for (int j = 0; j < 4; j++) {
        long row = (long)blockIdx.x * GROWS + rx * 4 + j;
#pragma unroll
        for (int i = 0; i < 6; i++) {
            int c = cx * 6 + i;
            float v = acc[j][i] + bs[c];
            if (c < CACT) out[row * CACT + c] = v;
            else          out_time[row * CTIME + (c - CACT)] = v;
        }
    }
}

// ---------------------------------------------------------------------------
// Prototype causal scan. One block per (batch, head). Only LABEL positions do
// work (~20 per sequence). Per-class counts cancel inside l2norm -> only the
// total support count matters for validity.
// ---------------------------------------------------------------------------
__global__ void proto_kernel(const int* __restrict__ tokens,
                             const float* __restrict__ h,
                             float* __restrict__ out)
{
    extern __shared__ float sm[];
    int b = blockIdx.x >> 1;
    int kind = blockIdx.x & 1;             // 0 = act, 1 = time
    int C   = kind ? CTIME : CACT;
    int lo  = kind ? TIME_START_ : ACT_START_;
    int hi  = kind ? VOCAB_ : TIME_START_;

    float* Hsum = sm;                      // reserve CACT*Ddim always
    float* hn   = sm + CACT * Ddim;        // 256
    float* red  = hn + Ddim;               // 16
    int*   toks = (int*)(red + 16);        // 2048
    __shared__ float cnt_total;

    int tid = threadIdx.x;
    for (int i = tid; i < C * Ddim; i += 256) Hsum[i] = 0.f;
    for (int i = tid; i < Tdim; i += 256) toks[i] = tokens[(long)b * Tdim + i];
    if (tid == 0) cnt_total = 0.f;
    __syncthreads();

    float alpha = g_scal[2 + kind];
    float scale = g_scal[kind];
    const float* En = g_En + (kind ? CACT * Ddim : 0);
    float* outb = kind ? (out + (long)Bdim * Tdim * CACT + (long)b * Tdim * CTIME)
                       : (out + (long)b * Tdim * CACT);
    int outC = kind ? CTIME : CACT;

    int wid = tid >> 5, lane = tid & 31;

    for (int t = 0; t < Tdim; t++) {
        if (toks[t] != LABEL_ID_) continue;
        int ntok = toks[(t + 1) & (Tdim - 1)];   // jnp.roll wraps

        // normalize h[b,t,:]
        float hv = h[((long)b * Tdim + t) * Ddim + tid];
        float ss = hv * hv;
#pragma unroll
        for (int o = 16; o > 0; o >>= 1) ss += __shfl_xor_sync(0xffffffffu, ss, o);
        if (lane == 0) red[wid] = ss;
        bool have = cnt_total > 0.f;   // stable since last event's sync
        __syncthreads();
        if (tid == 0) {
            float s = 0.f;
#pragma unroll
            for (int i = 0; i < 8; i++) s += red[i];
            red[8] = 1.0f / fmaxf(sqrtf(s), 1e-12f);
        }
        __syncthreads();
        hn[tid] = hv * red[8];
        __syncthreads();

        if (have) {
            // warps split the classes; lane covers 8 d-values (stride 32)
            for (int c = wid; c < C; c += 8) {
                const float* Hc = Hsum + c * Ddim;
                const float* Ec = En + (long)c * Ddim;
                float s1 = 0.f, s2 = 0.f;
#pragma unroll
                for (int k = 0; k < 8; k++) {
                    int d = lane + 32 * k;
                    float v = Hc[d] + alpha * Ec[d];
                    s1 += v * hn[d];
                    s2 += v * v;
                }
#pragma unroll
                for (int o = 16; o > 0; o >>= 1) {
                    s1 += __shfl_xor_sync(0xffffffffu, s1, o);
                    s2 += __shfl_xor_sync(0xffffffffu, s2, o);
                }
                if (lane == 0) {
                    float sim = s1 / fmaxf(sqrtf(s2), 1e-12f);
                    outb[(long)t * outC + c] += scale * sim;
                }
            }
        }
        __syncthreads();   // all reads of Hsum done before update

        if (ntok >= lo && ntok < hi) {
            int cls = ntok - lo;
            Hsum[cls * Ddim + tid] += hn[tid];
            if (tid == 0) cnt_total += 1.f;
        }
        __syncthreads();
    }
}

// ---------------------------------------------------------------------------
extern "C" void kernel_launch(void* const* d_in, const int* in_sizes, int n_in,
                              void* d_out, int out_size)
{
    const int*   tokens = (const int*)d_in[0];
    const float* h      = (const float*)d_in[1];
    const float* E      = (const float*)d_in[2];
    const float* Wn     = (const float*)d_in[3];
    const float* bn     = (const float*)d_in[4];
    const float* Wt     = (const float*)d_in[5];
    const float* bt     = (const float*)d_in[6];

    size_t gemm_smem  = (size_t)(Ddim * NCOL + GROWS * HPAD + NCOL) * sizeof(float);
    size_t proto_smem = (size_t)(CACT * Ddim + Ddim + 16) * sizeof(float) + Tdim * sizeof(int);

    cudaFuncSetAttribute(gemm_kernel, cudaFuncAttributeMaxDynamicSharedMemorySize, (int)gemm_smem);
    cudaFuncSetAttribute(proto_kernel, cudaFuncAttributeMaxDynamicSharedMemorySize, (int)proto_smem);

    prep_kernel<<<1, 256>>>(E, Wn, bn, Wt, bt,
                            (const float*)d_in[7],  (const float*)d_in[8],
                            (const float*)d_in[9],  (const float*)d_in[10],
                            (const float*)d_in[11], (const float*)d_in[12],
                            (const float*)d_in[13], (const float*)d_in[14]);

    gemm_kernel<<<(Bdim * Tdim) / GROWS, 256, gemm_smem>>>(h, (float*)d_out);

    proto_kernel<<<Bdim * 2, 256, proto_smem>>>(tokens, h, (float*)d_out);
}

// round 2
// speedup vs baseline: 2.3788x; 2.3788x over previous
#include <cuda_runtime.h>
#include <math.h>

#define Bdim 8
#define Tdim 2048
#define Ddim 256
#define CACT 64
#define CTIME 32
#define NCOL 96
#define LABEL_ID_ 3
#define ACT_START_ 4
#define TIME_START_ 68
#define VOCAB_ 100
#define NROWS (Bdim * Tdim)

typedef unsigned long long ull;

// device scratch (no allocations allowed)
__device__ float g_WcT[Ddim * NCOL];   // combined weights, [d][c]
__device__ float g_bias[NCOL];
__device__ float g_En[NCOL * Ddim];    // normalized E rows: 0..63 act, 64..95 time
__device__ float g_scal[4];            // [0] scale*temp act, [1] scale*temp time,
                                       // [2] alpha_act, [3] alpha_time

__device__ __forceinline__ float softplusf(float x) { return log1pf(expf(x)); }

__device__ __forceinline__ ull splat2(float x) {
    ull r;
    asm("mov.b64 %0, {%1, %1};" : "=l"(r) : "r"(__float_as_uint(x)));
    return r;
}
__device__ __forceinline__ ull fma2(ull a, ull b, ull c) {
    ull d;
    asm("fma.rn.f32x2 %0, %1, %2, %3;" : "=l"(d) : "l"(a), "l"(b), "l"(c));
    return d;
}

// ---------------------------------------------------------------------------
// Prep: grid = 128 blocks x 256 threads.
//  - every block: 2 d-slices of the folded weight matrix (coalesced writes)
//  - blocks 0..95: l2-normalize one E class row (fully coalesced)
//  - block 96: bias + scalars
// ---------------------------------------------------------------------------
__global__ void __launch_bounds__(256) prep_kernel(
    const float* __restrict__ E,
    const float* __restrict__ Wn, const float* __restrict__ bn,
    const float* __restrict__ Wt, const float* __restrict__ bt,
    const float* __restrict__ tsa, const float* __restrict__ tst,
    const float* __restrict__ psa, const float* __restrict__ pst,
    const float* __restrict__ ppa, const float* __restrict__ ppt,
    const float* __restrict__ pta, const float* __restrict__ ptt)
{
    int tid = threadIdx.x, bid = blockIdx.x;
    float s_ta = softplusf(*tsa);
    float s_tt = softplusf(*tst);

    // folded weights: block handles d = 2*bid, 2*bid+1
    if (tid < 2 * NCOL) {
        int half = tid / NCOL;
        int c = tid - half * NCOL;
        int d = 2 * bid + half;
        float w;
        if (c < CACT) w = Wn[c * Ddim + d] + s_ta * E[(ACT_START_ + c) * Ddim + d];
        else {
            int cc = c - CACT;
            w = Wt[cc * Ddim + d] + s_tt * E[(TIME_START_ + cc) * Ddim + d];
        }
        g_WcT[d * NCOL + c] = w;
    }

    // normalized class embeddings: block = class row, coalesced
    if (bid < NCOL) {
        __shared__ float sred[8];
        __shared__ float sinv;
        int row = (bid < CACT) ? (ACT_START_ + bid) : (TIME_START_ + (bid - CACT));
        float v = E[row * Ddim + tid];
        float ss = v * v;
#pragma unroll
        for (int o = 16; o > 0; o >>= 1) ss += __shfl_xor_sync(0xffffffffu, ss, o);
        if ((tid & 31) == 0) sred[tid >> 5] = ss;
        __syncthreads();
        if (tid == 0) {
            float s = 0.f;
#pragma unroll
            for (int i = 0; i < 8; i++) s += sred[i];
            sinv = 1.0f / fmaxf(sqrtf(s), 1e-12f);
        }
        __syncthreads();
        g_En[bid * Ddim + tid] = v * sinv;
    }

    if (bid == 96) {
        if (tid < NCOL) g_bias[tid] = (tid < CACT) ? bn[tid] : bt[tid - CACT];
        if (tid == 128) {
            g_scal[0] = softplusf(*psa) * softplusf(*pta);
            g_scal[1] = softplusf(*pst) * softplusf(*ptt);
            g_scal[2] = softplusf(*ppa);
            g_scal[3] = softplusf(*ppt);
        }
    }
}

// ---------------------------------------------------------------------------
// GEMM: out[row, 0..95] = h[row,:] @ Wc + bias.
// 128 blocks x 256 threads, 128 rows/block, split-K in 2 stages of 128.
// Per-thread tile: 4 rows x 12 cols using packed fp32x2 FFMA (col pairs).
// ---------------------------------------------------------------------------
#define GROWS 128
#define KHALF 128
#define HSTR 129   // odd stride: conflict-free h loads

__global__ void __launch_bounds__(256) gemm_kernel(const float* __restrict__ h,
                                                   float* __restrict__ out)
{
    extern __shared__ float sm[];
    float* sW = sm;                        // KHALF * 96
    float* hs = sm + KHALF * NCOL;         // GROWS * HSTR
    float* bs = hs + GROWS * HSTR;         // 96
    int tid = threadIdx.x;
    int cx = tid & 7;    // 8 col groups x 12 cols
    int rx = tid >> 3;   // 32 row groups x 4 rows

    if (tid < NCOL) bs[tid] = g_bias[tid];

    ull acc[4][6];
#pragma unroll
    for (int j = 0; j < 4; j++)
#pragma unroll
        for (int i = 0; i < 6; i++) acc[j][i] = 0ull;

    long rowbase = (long)blockIdx.x * GROWS;
    const float4* gh = (const float4*)h;

    for (int stage = 0; stage < 2; ++stage) {
        __syncthreads();   // previous-iteration reads done
        // stage weights (contiguous copy)
        {
            const float4* gw = (const float4*)(g_WcT + stage * KHALF * NCOL);
            float4* sw4 = (float4*)sW;
#pragma unroll
            for (int i = 0; i < (KHALF * NCOL) / (4 * 256); ++i)
                sw4[tid + 256 * i] = gw[tid + 256 * i];
        }
        // stage h half: coalesced global float4 reads, scalar smem writes
#pragma unroll
        for (int it = 0; it < (GROWS * KHALF) / (4 * 256); ++it) {
            int i = tid + 256 * it;
            int r = i >> 5, d4 = i & 31;
            float4 v = gh[(rowbase + r) * (Ddim / 4) + stage * (KHALF / 4) + d4];
            float* p = hs + r * HSTR + 4 * d4;
            p[0] = v.x; p[1] = v.y; p[2] = v.z; p[3] = v.w;
        }
        __syncthreads();

        const float* hp = hs + (rx * 4) * HSTR;
        const float* wp = sW + cx * 12;
#pragma unroll 4
        for (int d = 0; d < KHALF; ++d) {
            ull w[6];
            const ull* wrow = (const ull*)(wp + d * NCOL);
#pragma unroll
            for (int i = 0; i < 6; ++i) w[i] = wrow[i];
#pragma unroll
            for (int j = 0; j < 4; ++j) {
                ull s = splat2(hp[j * HSTR + d]);
#pragma unroll
                for (int i = 0; i < 6; ++i) acc[j][i] = fma2(w[i], s, acc[j][i]);
            }
        }
    }

    float* outT = out + (long)NROWS * CACT;
#pragma unroll
    for (int j = 0; j < 4; ++j) {
        long row = rowbase + rx * 4 + j;
#pragma unroll
        for (int i = 0; i < 6; ++i) {
            union { ull u; float2 f; } u;
            u.u = acc[j][i];
            int c0 = cx * 12 + 2 * i;
            float v0 = u.f.x + bs[c0];
            float v1 = u.f.y + bs[c0 + 1];
            if (c0 < CACT) out[row * CACT + c0] = v0;
            else           outT[row * CTIME + (c0 - CACT)] = v0;
            if (c0 + 1 < CACT) out[row * CACT + c0 + 1] = v1;
            else               outT[row * CTIME + (c0 + 1 - CACT)] = v1;
        }
    }
}

// ---------------------------------------------------------------------------
// Prototype causal scan. One block per (batch, head). Label events compacted
// once by warp ballot; q_c = Hsum_c + alpha*E_c and |q_c|^2 kept incrementally.
// ---------------------------------------------------------------------------
__global__ void __launch_bounds__(256) proto_kernel(const int* __restrict__ tokens,
                                                    const float* __restrict__ h,
                                                    float* __restrict__ out)
{
    extern __shared__ float sm[];
    int b = blockIdx.x >> 1;
    int kind = blockIdx.x & 1;             // 0 = act, 1 = time
    int C  = kind ? CTIME : CACT;
    int lo = kind ? TIME_START_ : ACT_START_;
    int hi = kind ? VOCAB_ : TIME_START_;

    float* q    = sm;                      // CACT*Ddim reserved
    float* hn   = sm + CACT * Ddim;        // 256
    float* red  = hn + Ddim;               // 16
    float* n2   = red + 16;                // 64
    int*   ev_t = (int*)(n2 + 64);         // 2048
    int*   ev_n = ev_t + Tdim;             // 2048
    int*   toks = ev_n + Tdim;             // 2048
    __shared__ int s_nev;

    int tid = threadIdx.x, wid = tid >> 5, lane = tid & 31;

    for (int i = tid; i < Tdim; i += 256) toks[i] = tokens[(long)b * Tdim + i];
    __syncthreads();

    if (wid == 0) {
        int cnt = 0;
        for (int ch = 0; ch < Tdim / 32; ++ch) {
            int t = ch * 32 + lane;
            bool isl = (toks[t] == LABEL_ID_);
            unsigned m = __ballot_sync(0xffffffffu, isl);
            if (isl) {
                int idx = cnt + __popc(m & ((1u << lane) - 1u));
                ev_t[idx] = t;
                ev_n[idx] = toks[(t + 1) & (Tdim - 1)];
            }
            cnt += __popc(m);
        }
        if (lane == 0) s_nev = cnt;
    }

    float alpha = g_scal[2 + kind];
    const float* En = g_En + (kind ? CACT * Ddim : 0);
    for (int i = tid; i < C * Ddim; i += 256) q[i] = alpha * En[i];
    for (int i = tid; i < C; i += 256) n2[i] = alpha * alpha;
    __syncthreads();

    int nev = s_nev;
    float scale = g_scal[kind];
    int outC = kind ? CTIME : CACT;
    float* outb = kind ? (out + (long)NROWS * CACT + (long)b * Tdim * CTIME)
                       : (out + (long)b * Tdim * CACT);
    const float* hb = h + (long)b * Tdim * Ddim;

    int cnt = 0;
    float hv = (nev > 0) ? hb[(long)ev_t[0] * Ddim + tid] : 0.f;

    for (int e = 0; e < nev; ++e) {
        int t = ev_t[e], ntok = ev_n[e];

        float ss = hv * hv;
#pragma unroll
        for (int o = 16; o > 0; o >>= 1) ss += __shfl_xor_sync(0xffffffffu, ss, o);
        if (lane == 0) red[wid] = ss;
        __syncthreads();
        if (tid == 0) {
            float s = 0.f;
#pragma unroll
            for (int i = 0; i < 8; i++) s += red[i];
            float inv = 1.0f / fmaxf(sqrtf(s), 1e-12f);
            red[8] = inv;
            red[9] = s * inv * inv;    // |hn|^2
        }
        __syncthreads();
        float inv = red[8];
        float hn2 = red[9];
        hn[tid] = hv * inv;
        __syncthreads();

        // prefetch next event's h row (hides DRAM/L2 latency behind sims)
        if (e + 1 < nev) hv = hb[(long)ev_t[e + 1] * Ddim + tid];

        bool sup = (ntok >= lo) && (ntok < hi);

        if (cnt > 0) {
            for (int c = wid; c < C; c += 8) {
                const float* qc = q + c * Ddim;
                float s1 = 0.f;
#pragma unroll
                for (int k = 0; k < 8; ++k) {
                    int d = lane + 32 * k;
                    s1 += qc[d] * hn[d];
                }
#pragma unroll
                for (int o = 16; o > 0; o >>= 1) s1 += __shfl_xor_sync(0xffffffffu, s1, o);
                if (lane == 0) {
                    float sim = s1 / sqrtf(n2[c]);   // n2 >= alpha^2 > 0
                    outb[(long)t * outC + c] += scale * sim;
                }
            }
        }
        __syncthreads();   // sims reads of q done before update

        if (sup) {
            int cls = ntok - lo;
            if (wid == 0) {
                float dq = 0.f;
#pragma unroll
                for (int k = 0; k < 8; ++k) {
                    int d = lane + 32 * k;
                    dq += q[cls * Ddim + d] * hn[d];
                }
#pragma unroll
                for (int o = 16; o > 0; o >>= 1) dq += __shfl_xor_sync(0xffffffffu, dq, o);
                if (lane == 0) n2[cls] += 2.f * dq + hn2;
            }
            __syncthreads();   // dq read before q changes
            q[cls * Ddim + tid] += hn[tid];
            cnt++;
        }
        __syncthreads();
    }
}

// ---------------------------------------------------------------------------
extern "C" void kernel_launch(void* const* d_in, const int* in_sizes, int n_in,
                              void* d_out, int out_size)
{
    const int*   tokens = (const int*)d_in[0];
    const float* h      = (const float*)d_in[1];
    const float* E      = (const float*)d_in[2];
    const float* Wn     = (const float*)d_in[3];
    const float* bn     = (const float*)d_in[4];
    const float* Wt     = (const float*)d_in[5];
    const float* bt     = (const float*)d_in[6];

    size_t gemm_smem  = (size_t)(KHALF * NCOL + GROWS * HSTR + NCOL) * sizeof(float);
    size_t proto_smem = (size_t)(CACT * Ddim + Ddim + 16 + 64) * sizeof(float)
                      + (size_t)3 * Tdim * sizeof(int);

    cudaFuncSetAttribute(gemm_kernel, cudaFuncAttributeMaxDynamicSharedMemorySize, (int)gemm_smem);
    cudaFuncSetAttribute(proto_kernel, cudaFuncAttributeMaxDynamicSharedMemorySize, (int)proto_smem);

    prep_kernel<<<128, 256>>>(E, Wn, bn, Wt, bt,
                              (const float*)d_in[7],  (const float*)d_in[8],
                              (const float*)d_in[9],  (const float*)d_in[10],
                              (const float*)d_in[11], (const float*)d_in[12],
                              (const float*)d_in[13], (const float*)d_in[14]);

    gemm_kernel<<<NROWS / GROWS, 256, gemm_smem>>>(h, (float*)d_out);

    proto_kernel<<<Bdim * 2, 256, proto_smem>>>(tokens, h, (float*)d_out);
}

// round 3
// speedup vs baseline: 5.3967x; 2.2687x over previous
#include <cuda_runtime.h>
#include <math.h>

#define Bdim 8
#define Tdim 2048
#define Ddim 256
#define CACT 64
#define CTIME 32
#define NCOL 96
#define NROWS (Bdim * Tdim)
#define LABEL_ID_ 3
#define ACT_START_ 4
#define TIME_START_ 68
#define VOCAB_ 100

#define GBLOCKS 128
#define GROWS 128
#define KHALF 128
#define SWSTR 98     // padded [d][c] weight stride: varies banks, 8B aligned
#define HSTR 132     // padded h row stride: float4-aligned, bank-varying

typedef unsigned long long ull;

// device scratch (static, no allocations)
__device__ float g_scr[(long)NROWS * NCOL];
__device__ unsigned char g_flags[NROWS];

__device__ __forceinline__ float softplusf(float x) { return log1pf(expf(x)); }

__device__ __forceinline__ ull splat2(float x) {
    ull r;
    asm("mov.b64 %0, {%1, %1};" : "=l"(r) : "r"(__float_as_uint(x)));
    return r;
}
__device__ __forceinline__ ull fma2(ull a, ull b, ull c) {
    ull d;
    asm("fma.rn.f32x2 %0, %1, %2, %3;" : "=l"(d) : "l"(a), "l"(b), "l"(c));
    return d;
}

// ---------------------------------------------------------------------------
// Fat kernel: blocks 0..127 = GEMM role, blocks 128..143 = proto role.
// Roles are independent (proto -> scratch+flags), so they run concurrently.
// ---------------------------------------------------------------------------
__global__ void __launch_bounds__(512, 1) fat_kernel(
    const int* __restrict__ tokens, const float* __restrict__ h,
    const float* __restrict__ E,
    const float* __restrict__ Wn, const float* __restrict__ bn,
    const float* __restrict__ Wt, const float* __restrict__ bt,
    const float* __restrict__ tsa, const float* __restrict__ tst,
    const float* __restrict__ psa, const float* __restrict__ pst,
    const float* __restrict__ ppa, const float* __restrict__ ppt,
    const float* __restrict__ pta, const float* __restrict__ ptt,
    float* __restrict__ out)
{
    extern __shared__ float sm[];
    int tid = threadIdx.x;

    if (blockIdx.x < GBLOCKS) {
        // =================== GEMM role ===================
        float* sW = sm;                       // KHALF * SWSTR
        float* hs = sm + KHALF * SWSTR;       // GROWS * HSTR
        float* bs = hs + GROWS * HSTR;        // NCOL

        float s_ta = softplusf(*tsa);
        float s_tt = softplusf(*tst);
        if (tid < NCOL) bs[tid] = (tid < CACT) ? bn[tid] : bt[tid - CACT];

        ull acc[12];
#pragma unroll
        for (int i = 0; i < 12; ++i) acc[i] = 0ull;

        long rowbase = (long)blockIdx.x * GROWS;
        const float4* gh = (const float4*)h;

        for (int stage = 0; stage < 2; ++stage) {
            __syncthreads();
            // ---- fold weights: sW[d][c] = W[c][d] + s*E[row_c][d] ----
            {
                float4 wv[6], evv[6];
#pragma unroll
                for (int k = 0; k < 6; ++k) {
                    int i = tid + 512 * k;
                    int c = i % 96, d4 = i / 96;
                    const float* wrow; int erow;
                    if (c < CACT) { wrow = Wn + c * Ddim; erow = ACT_START_ + c; }
                    else          { wrow = Wt + (c - CACT) * Ddim; erow = TIME_START_ + (c - CACT); }
                    wv[k]  = ((const float4*)wrow)[stage * 32 + d4];
                    evv[k] = ((const float4*)(E + (long)erow * Ddim))[stage * 32 + d4];
                }
#pragma unroll
                for (int k = 0; k < 6; ++k) {
                    int i = tid + 512 * k;
                    int c = i % 96, d4 = i / 96;
                    float sc = (c < CACT) ? s_ta : s_tt;
                    float* p = sW + c;
                    int db = 4 * d4;
                    p[(db + 0) * SWSTR] = wv[k].x + sc * evv[k].x;
                    p[(db + 1) * SWSTR] = wv[k].y + sc * evv[k].y;
                    p[(db + 2) * SWSTR] = wv[k].z + sc * evv[k].z;
                    p[(db + 3) * SWSTR] = wv[k].w + sc * evv[k].w;
                }
            }
            // ---- stage h half ----
#pragma unroll
            for (int it = 0; it < 8; ++it) {
                int i = tid + 512 * it;
                int r = i >> 5, d4 = i & 31;
                float4 v = gh[(rowbase + r) * (Ddim / 4) + stage * (KHALF / 4) + d4];
                *(float4*)(hs + r * HSTR + 4 * d4) = v;
            }
            __syncthreads();

            // ---- compute: 2 rows x 12 cols per thread, packed fp32x2 FMA ----
            int cx = tid & 7;      // 8 col groups * 12
            int rx = tid >> 3;     // 64 row groups * 2
            const float* hp = hs + (rx * 2) * HSTR;
            const float* wp = sW + cx * 12;
#pragma unroll 4
            for (int d = 0; d < KHALF; ++d) {
                const ull* wrow = (const ull*)(wp + d * SWSTR);
                ull w0 = wrow[0], w1 = wrow[1], w2 = wrow[2];
                ull w3 = wrow[3], w4 = wrow[4], w5 = wrow[5];
                ull s0 = splat2(hp[d]);
                ull s1 = splat2(hp[HSTR + d]);
                acc[0]  = fma2(w0, s0, acc[0]);  acc[1]  = fma2(w1, s0, acc[1]);
                acc[2]  = fma2(w2, s0, acc[2]);  acc[3]  = fma2(w3, s0, acc[3]);
                acc[4]  = fma2(w4, s0, acc[4]);  acc[5]  = fma2(w5, s0, acc[5]);
                acc[6]  = fma2(w0, s1, acc[6]);  acc[7]  = fma2(w1, s1, acc[7]);
                acc[8]  = fma2(w2, s1, acc[8]);  acc[9]  = fma2(w3, s1, acc[9]);
                acc[10] = fma2(w4, s1, acc[10]); acc[11] = fma2(w5, s1, acc[11]);
            }
        }

        // ---- store ----
        int cx = tid & 7;
        int rx = tid >> 3;
        float* outT = out + (long)NROWS * CACT;
#pragma unroll
        for (int j = 0; j < 2; ++j) {
            long row = rowbase + rx * 2 + j;
#pragma unroll
            for (int i = 0; i < 6; ++i) {
                union { ull u; float2 f; } u;
                u.u = acc[j * 6 + i];
                int c0 = cx * 12 + 2 * i;
                float v0 = u.f.x + bs[c0];
                float v1 = u.f.y + bs[c0 + 1];
                if (c0 < CACT) out[row * CACT + c0] = v0;
                else           outT[row * CTIME + (c0 - CACT)] = v0;
                if (c0 + 1 < CACT) out[row * CACT + c0 + 1] = v1;
                else               outT[row * CTIME + (c0 + 1 - CACT)] = v1;
            }
        }
    } else {
        // =================== proto role ===================
        int pb = blockIdx.x - GBLOCKS;       // 0..15
        int b = pb >> 1;
        int kind = pb & 1;                   // 0 = act, 1 = time
        int C  = kind ? CTIME : CACT;
        int lo = kind ? TIME_START_ : ACT_START_;
        int hi = kind ? VOCAB_ : TIME_START_;

        float* q    = sm;                     // CACT*Ddim reserved
        float* hn   = sm + CACT * Ddim;       // 256
        float* red  = hn + Ddim;              // 16
        float* n2   = red + 16;               // 64
        int*   ev_t = (int*)(n2 + 64);        // 2048
        int*   ev_n = ev_t + Tdim;            // 2048
        int*   toks = ev_n + Tdim;            // 2048
        __shared__ int s_nev;
        __shared__ float s_dq;

        int wid = tid >> 5, lane = tid & 31;

        for (int i = tid; i < Tdim; i += 512) toks[i] = tokens[(long)b * Tdim + i];
        __syncthreads();

        if (wid == 0) {
            int cnt = 0;
            for (int ch = 0; ch < Tdim / 32; ++ch) {
                int t = ch * 32 + lane;
                bool isl = (toks[t] == LABEL_ID_);
                unsigned m = __ballot_sync(0xffffffffu, isl);
                if (isl) {
                    int idx = cnt + __popc(m & ((1u << lane) - 1u));
                    ev_t[idx] = t;
                    ev_n[idx] = toks[(t + 1) & (Tdim - 1)];
                }
                cnt += __popc(m);
            }
            if (lane == 0) s_nev = cnt;
        }
        if (kind == 0) {
            for (int i = tid; i < Tdim; i += 512)
                g_flags[b * Tdim + i] = (toks[i] == LABEL_ID_) ? 1 : 0;
        }

        float alpha = softplusf(kind ? *ppt : *ppa);
        float scale = softplusf(kind ? *pst : *psa) * softplusf(kind ? *ptt : *pta);

        // init q rows = alpha * normalized E class rows (warp per row)
        for (int r = wid; r < C; r += 16) {
            int erow = (kind ? TIME_START_ : ACT_START_) + r;
            const float* e = E + (long)erow * Ddim;
            float v[8]; float ss = 0.f;
#pragma unroll
            for (int k = 0; k < 8; ++k) { v[k] = e[lane + 32 * k]; ss += v[k] * v[k]; }
#pragma unroll
            for (int o = 16; o > 0; o >>= 1) ss += __shfl_xor_sync(0xffffffffu, ss, o);
            float inv = alpha / fmaxf(sqrtf(ss), 1e-12f);
#pragma unroll
            for (int k = 0; k < 8; ++k) q[r * Ddim + lane + 32 * k] = v[k] * inv;
        }
        if (tid < C) n2[tid] = alpha * alpha;
        __syncthreads();

        int nev = s_nev;
        const float* hb = h + (long)b * Tdim * Ddim;
        float* scr = g_scr + (long)b * Tdim * NCOL + (kind ? CACT : 0);

        int cnt = 0;
        float hv = 0.f;
        if (nev > 0 && tid < Ddim) hv = hb[(long)ev_t[0] * Ddim + tid];

        for (int e = 0; e < nev; ++e) {
            int t = ev_t[e], ntok = ev_n[e];

            // ---- normalize h row ----
            if (tid < Ddim) {
                float ss = hv * hv;
#pragma unroll
                for (int o = 16; o > 0; o >>= 1) ss += __shfl_xor_sync(0xffffffffu, ss, o);
                if (lane == 0) red[wid] = ss;
            }
            __syncthreads();
            if (tid == 0) {
                float s = 0.f;
#pragma unroll
                for (int i = 0; i < 8; ++i) s += red[i];
                float inv = 1.0f / fmaxf(sqrtf(s), 1e-12f);
                red[8] = inv;
                red[9] = s * inv * inv;     // |hn|^2
            }
            __syncthreads();
            if (tid < Ddim) hn[tid] = hv * red[8];
            __syncthreads();
            float hn2 = red[9];
            if (tid < Ddim && e + 1 < nev) hv = hb[(long)ev_t[e + 1] * Ddim + tid];

            bool sup = (ntok >= lo) && (ntok < hi);
            int cls = ntok - lo;

            // ---- sims: lane-parallel partial dots, bank-rotated ----
            if (!kind) {
                int c = tid >> 3, seg = tid & 7;
                const float* qc = q + c * Ddim + seg * 32;
                const float* hc = hn + seg * 32;
                float s1 = 0.f;
#pragma unroll
                for (int i = 0; i < 32; ++i) {
                    int dd = (i + lane) & 31;
                    s1 += qc[dd] * hc[dd];
                }
#pragma unroll
                for (int o = 1; o < 8; o <<= 1) s1 += __shfl_xor_sync(0xffffffffu, s1, o);
                if (seg == 0) {
                    if (sup && c == cls) s_dq = s1;
                    float val = (cnt > 0) ? scale * s1 * rsqrtf(n2[c]) : 0.f;
                    scr[(long)t * NCOL + c] = val;
                }
            } else {
                int c = tid >> 4, seg = tid & 15;
                const float* qc = q + c * Ddim + seg * 16;
                const float* hc = hn + seg * 16;
                float s1 = 0.f;
#pragma unroll
                for (int i = 0; i < 16; ++i) {
                    int dd = (i + (lane >> 1)) & 15;
                    s1 += qc[dd] * hc[dd];
                }
#pragma unroll
                for (int o = 1; o < 16; o <<= 1) s1 += __shfl_xor_sync(0xffffffffu, s1, o);
                if (seg == 0) {
                    if (sup && c == cls) s_dq = s1;
                    float val = (cnt > 0) ? scale * s1 * rsqrtf(n2[c]) : 0.f;
                    scr[(long)t * NCOL + c] = val;
                }
            }
            __syncthreads();   // q reads + s_dq write done

            if (sup) {
                if (tid < Ddim) q[cls * Ddim + tid] += hn[tid];
                if (tid == 0) n2[cls] += 2.f * s_dq + hn2;
                cnt++;
            }
            __syncthreads();
        }
    }
}

// ---------------------------------------------------------------------------
// Epilogue: add proto scratch into out at flagged (label) rows.
// ---------------------------------------------------------------------------
__global__ void __launch_bounds__(512) epi_kernel(float* __restrict__ out)
{
    int row = blockIdx.x * 512 + threadIdx.x;
    if (g_flags[row]) {
        const float* s = g_scr + (long)row * NCOL;
        float* oa = out + (long)row * CACT;
#pragma unroll
        for (int c = 0; c < CACT; ++c) oa[c] += s[c];
        float* ot = out + (long)NROWS * CACT + (long)row * CTIME;
#pragma unroll
        for (int c = 0; c < CTIME; ++c) ot[c] += s[CACT + c];
    }
}

// ---------------------------------------------------------------------------
extern "C" void kernel_launch(void* const* d_in, const int* in_sizes, int n_in,
                              void* d_out, int out_size)
{
    const int*   tokens = (const int*)d_in[0];
    const float* h      = (const float*)d_in[1];
    const float* E      = (const float*)d_in[2];
    const float* Wn     = (const float*)d_in[3];
    const float* bn     = (const float*)d_in[4];
    const float* Wt     = (const float*)d_in[5];
    const float* bt     = (const float*)d_in[6];

    size_t smem = (size_t)(KHALF * SWSTR + GROWS * HSTR + NCOL) * sizeof(float);
    cudaFuncSetAttribute(fat_kernel, cudaFuncAttributeMaxDynamicSharedMemorySize, (int)smem);

    fat_kernel<<<GBLOCKS + 16, 512, smem>>>(
        tokens, h, E, Wn, bn, Wt, bt,
        (const float*)d_in[7],  (const float*)d_in[8],
        (const float*)d_in[9],  (const float*)d_in[10],
        (const float*)d_in[11], (const float*)d_in[12],
        (const float*)d_in[13], (const float*)d_in[14],
        (float*)d_out);

    epi_kernel<<<NROWS / 512, 512>>>((float*)d_out);
}